// round 15
// baseline (speedup 1.0000x reference)
#include <cuda_runtime.h>
#include <cuda_fp16.h>
#include <cstdint>

#define B_ 2
#define L_ 4800
#define S_ 4800
#define C_ 256
#define NT_ 38          // n-tiles of 128
#define NSPLIT 4        // n-range splits -> 4*38*2 = 304 CTAs (2/SM, one wave)
#define SMPAD 36        // proj kernel smem pad (floats)
#define BL_ (B_ * L_)

// ---- proj smem: 2 stages x (A + B) x 128 rows x SMPAD floats ----
#define PSTAGEF (128 * SMPAD)                    // floats per operand tile
#define PROJ_SMEM (2 * 2 * PSTAGEF * 4)          // 73728 B

// ---- sim kernel smem geometry (fp16, M=128 resident A) ----
#define ASTRIDE 264                      // halves per A smem row (256 data + 8 pad)
#define HSTRIDE 72                       // halves per B smem row (64 data + 8 pad)
#define ABYTES  (128 * ASTRIDE * 2)      // resident A tile: 67584 B
#define BCHUNKB (128 * HSTRIDE * 2)      // one B chunk: 18432 B
#define DYN_SZ  (ABYTES + 2 * BCHUNKB)   // 104448 B  (x2 CTAs = 204 KB/SM)

// ---------------- scratch (device globals: no allocs allowed) ----------------
__device__ __half g_f0h[B_ * L_ * C_];
__device__ __half g_f1h[B_ * S_ * C_];
__device__ __half g_simh[(size_t)B_ * L_ * S_];         // E = exp(logit), fp16 (92 MB)
__device__ float  g_rmax[BL_];
__device__ float  g_rsum[BL_];
__device__ float  g_cmax[B_ * S_];
__device__ float  g_csum[B_ * S_];
__device__ unsigned char g_bord0[L_];
__device__ unsigned char g_bord1[S_];
__device__ int    g_marker;

__device__ __forceinline__ float tf32r(float x) {
    uint32_t u = __float_as_uint(x);
    asm("cvt.rna.tf32.f32 %0, %0;" : "+r"(u));
    return __uint_as_float(u);
}

// tf32 m16n8k8 (proj only)
__device__ __forceinline__ void mma8(float d[4], const uint32_t a[4], const uint32_t b[2]) {
    asm volatile(
        "mma.sync.aligned.m16n8k8.row.col.f32.tf32.tf32.f32 "
        "{%0,%1,%2,%3}, {%4,%5,%6,%7}, {%8,%9}, {%0,%1,%2,%3};"
        : "+f"(d[0]), "+f"(d[1]), "+f"(d[2]), "+f"(d[3])
        : "r"(a[0]), "r"(a[1]), "r"(a[2]), "r"(a[3]), "r"(b[0]), "r"(b[1]));
}

// fp16 m16n8k16 (sim)
__device__ __forceinline__ void mma16(float d[4], uint32_t a0, uint32_t a1,
                                      uint32_t a2, uint32_t a3,
                                      uint32_t b0, uint32_t b1) {
    asm volatile(
        "mma.sync.aligned.m16n8k16.row.col.f32.f16.f16.f32 "
        "{%0,%1,%2,%3}, {%4,%5,%6,%7}, {%8,%9}, {%0,%1,%2,%3};"
        : "+f"(d[0]), "+f"(d[1]), "+f"(d[2]), "+f"(d[3])
        : "r"(a0), "r"(a1), "r"(a2), "r"(a3), "r"(b0), "r"(b1));
}

#define LDSM4(r0, r1, r2, r3, addr)                                            \
    asm volatile("ldmatrix.sync.aligned.m8n8.x4.shared.b16 {%0,%1,%2,%3}, [%4];" \
                 : "=r"(r0), "=r"(r1), "=r"(r2), "=r"(r3) : "r"(addr))

__device__ __forceinline__ float neginf() { return __int_as_float(0xff800000); }

__device__ __forceinline__ uint32_t smaddr(const void* p) {
    return (uint32_t)__cvta_generic_to_shared(p);
}

#define CP16(dst, src, pred)                                                   \
    asm volatile("cp.async.cg.shared.global [%0], [%1], 16, %2;\n" ::          \
                     "r"(dst), "l"(src), "r"((pred) ? 16 : 0))
#define CPCOMMIT() asm volatile("cp.async.commit_group;\n")
#define CPWAIT0()  asm volatile("cp.async.wait_group 0;\n")
#define PAIRBAR(id) asm volatile("bar.sync %0, 64;" :: "r"(id) : "memory")

// atomic max for strictly-positive floats via int bit-pattern ordering
__device__ __forceinline__ void atomicMaxPosF(float* addr, float v) {
    atomicMax(reinterpret_cast<int*>(addr), __float_as_int(v));
}

// ---------------- idx 0: border masks + zero stats (+ marker) ----------------
__global__ void init_kernel(const int* __restrict__ ph0, const int* __restrict__ pw0,
                            const int* __restrict__ ph1, const int* __restrict__ pw1)
{
    int h0 = __ldg(ph0), w0 = __ldg(pw0), h1 = __ldg(ph1), w1 = __ldg(pw1);
    int i = blockIdx.x * blockDim.x + threadIdx.x;
    if (i == 0) g_marker = 1;
    if (i < L_) {
        int r = i / w0, c = i - r * w0;
        g_bord0[i] = (r >= 2 && r < h0 - 2 && c >= 2 && c < w0 - 2) ? 1 : 0;
    } else if (i < L_ + S_) {
        int s = i - L_;
        int r = s / w1, c = s - r * w1;
        g_bord1[s] = (r >= 2 && r < h1 - 2 && c >= 2 && c < w1 - 2) ? 1 : 0;
    }
    // zero the atomic accumulators (every call: graph replays reuse them)
    if (i < BL_) {                  // B_*S_ == BL_
        g_rmax[i] = 0.f;
        g_rsum[i] = 0.f;
        g_cmax[i] = 0.f;
        g_csum[i] = 0.f;
    }
}

// ---------------- idx 2: tiny marker (keeps sim at position 3) ----------------
__global__ void marker_kernel() {
    if (threadIdx.x == 0) g_marker = 2;
}

// ================= proj (tf32, double-buffered, single sync/chunk) =================
__global__ __launch_bounds__(256) void proj_kernel(
    const float* __restrict__ X0, const float* __restrict__ X1,
    const float* __restrict__ W, const float* __restrict__ bias)
{
    extern __shared__ float ps[];   // [stage][A|B][128*SMPAD]

    const int which = blockIdx.z;
    const float* A = which ? X1 : X0;
    const int n0 = blockIdx.x * 128;
    const int m0 = blockIdx.y * 128;

    const int tid  = threadIdx.x;
    const int lane = tid & 31;
    const int warp = tid >> 5;
    const int wm = warp >> 2, wn = warp & 3;
    const int gp = lane >> 2, tg = lane & 3;

    float acc[4][4][4] = {};

    auto store_chunk = [&](int kc, int buf) {
        float* As = ps + buf * 2 * PSTAGEF;
        float* Bs = As + PSTAGEF;
        #pragma unroll
        for (int i = 0; i < 4; i++) {
            int idx = tid + i * 256;
            int r   = idx >> 3;
            int kq  = (idx & 7) * 4;
            float4 va = *reinterpret_cast<const float4*>(A + (size_t)(m0 + r) * C_ + kc + kq);
            va.x = tf32r(va.x); va.y = tf32r(va.y); va.z = tf32r(va.z); va.w = tf32r(va.w);
            *reinterpret_cast<float4*>(As + r * SMPAD + kq) = va;
            float4 vb = *reinterpret_cast<const float4*>(W + (size_t)(n0 + r) * C_ + kc + kq);
            vb.x = tf32r(vb.x); vb.y = tf32r(vb.y); vb.z = tf32r(vb.z); vb.w = tf32r(vb.w);
            *reinterpret_cast<float4*>(Bs + r * SMPAD + kq) = vb;
        }
    };

    store_chunk(0, 0);
    __syncthreads();

    for (int c = 0; c < 8; c++) {
        if (c < 7) store_chunk((c + 1) * 32, (c + 1) & 1);  // writes idle buffer

        const float* As = ps + (c & 1) * 2 * PSTAGEF;
        const float* Bs = As + PSTAGEF;
        #pragma unroll
        for (int ks = 0; ks < 4; ks++) {
            const int k0 = ks * 8;
            uint32_t afr[4][4];
            uint32_t bfr[4][2];
            #pragma unroll
            for (int mf = 0; mf < 4; mf++) {
                const float* p = As + (wm * 64 + mf * 16 + gp) * SMPAD + k0 + tg;
                afr[mf][0] = __float_as_uint(p[0]);
                afr[mf][1] = __float_as_uint(p[8 * SMPAD]);
                afr[mf][2] = __float_as_uint(p[4]);
                afr[mf][3] = __float_as_uint(p[8 * SMPAD + 4]);
            }
            #pragma unroll
            for (int nf = 0; nf < 4; nf++) {
                const float* p = Bs + (wn * 32 + nf * 8 + gp) * SMPAD + k0 + tg;
                bfr[nf][0] = __float_as_uint(p[0]);
                bfr[nf][1] = __float_as_uint(p[4]);
            }
            #pragma unroll
            for (int mf = 0; mf < 4; mf++)
                #pragma unroll
                for (int nf = 0; nf < 4; nf++)
                    mma8(acc[mf][nf], afr[mf], bfr[nf]);
        }
        __syncthreads();   // STS(c+1) visible; reads of buf c&1 complete
    }

    __half* O = which ? g_f1h : g_f0h;
    #pragma unroll
    for (int mf = 0; mf < 4; mf++) {
        int row = m0 + wm * 64 + mf * 16 + gp;
        #pragma unroll
        for (int nf = 0; nf < 4; nf++) {
            int col = n0 + wn * 32 + nf * 8 + 2 * tg;
            float b0 = __ldg(bias + col), b1 = __ldg(bias + col + 1);
            #pragma unroll
            for (int h = 0; h < 2; h++) {
                __half2 v = __floats2half2_rn(
                    (acc[mf][nf][2 * h]     + b0) * 0.0625f,
                    (acc[mf][nf][2 * h + 1] + b1) * 0.0625f);
                *reinterpret_cast<__half2*>(O + (size_t)(row + 8 * h) * C_ + col) = v;
            }
        }
    }
}

// ======== sim (persistent-A M=128, pair barriers, atomic stats, fp16 E) ========
__global__ __launch_bounds__(256, 2) void sim_kernel()
{
    extern __shared__ char dynp[];          // [A tile | B buf0 | B buf1]
    __shared__ float red_m[4 * 128];
    __shared__ float red_s[4 * 128];

    const int sidx = blockIdx.x;            // n-range split
    const int tm   = blockIdx.y;
    const int bb   = blockIdx.z;
    const int m0   = tm * 128;
    const __half* A  = g_f0h + (size_t)bb * L_ * C_;
    const __half* Bm = g_f1h + (size_t)bb * S_ * C_;

    const int tid  = threadIdx.x;
    const int lane = tid & 31;
    const int warp = tid >> 5;
    const int wm = warp >> 2, wn = warp & 3;
    const int gp = lane >> 2, tg = lane & 3;

    __half* Asm = (__half*)dynp;
    char*   Bbuf0 = dynp + ABYTES;

    // ---- resident A tile load ----
    {
        const int r    = tid >> 1;
        const int half = tid & 1;
        int gr = m0 + r; bool oa = gr < L_;
        const __half* arow = A + (size_t)(oa ? gr : 0) * C_;
        #pragma unroll
        for (int i = 0; i < 16; i++) {
            int seg = half * 16 + i;
            CP16(smaddr(Asm + r * ASTRIDE + seg * 8), arow + seg * 8, oa);
        }
    }
    CPCOMMIT();

    // ---- per-pair B slice loader ----
    const int tp   = wm * 32 + lane;
    const int brow = wn * 32 + (tp >> 1);
    const int bq0  = (tp & 1) * 4;
    auto load_bslice = [&](int tn, int c, int buf) {
        __half* Bb = (__half*)(Bbuf0 + buf * BCHUNKB);
        const int kc = c * 64;
        int gn = tn * 128 + brow; bool ob = gn < S_;
        const __half* brw = Bm + (size_t)(ob ? gn : 0) * C_ + kc;
        #pragma unroll
        for (int q = 0; q < 4; q++) {
            int kk = (bq0 + q) * 8;
            CP16(smaddr(Bb + brow * HSTRIDE + kk), brw + kk, ob);
        }
    };

    const uint32_t aoff = (uint32_t)((wm * 64 + (lane & 15)) * ASTRIDE + (lane >> 4) * 8) * 2;
    const uint32_t boff = (uint32_t)((wn * 32 + (lane & 7) + ((lane >> 4) & 1) * 8) * HSTRIDE
                                     + ((lane >> 3) & 1) * 8) * 2;
    const uint32_t Abase = smaddr(Asm) + aoff;

    int tnlist[10];
    int ntn = 0;
    for (int tn = sidx; tn < NT_; tn += NSPLIT) tnlist[ntn++] = tn;

    load_bslice(tnlist[0], 0, 0);
    CPCOMMIT();

    CPWAIT0();
    __syncthreads();    // publish A (one-time)

    float rmx[8], rsm[8];
    #pragma unroll
    for (int i = 0; i < 8; i++) { rmx[i] = neginf(); rsm[i] = 0.f; }

    const int ntot = ntn * 4;
    const int barid = wn + 1;
    int g = 0;

    for (int ti = 0; ti < ntn; ti++) {
        const int tn = tnlist[ti];
        const int n0 = tn * 128;
        float acc[4][4][4] = {};

        #pragma unroll
        for (int c = 0; c < 4; c++) {
            if (g > 0) {
                CPWAIT0();
                PAIRBAR(barid);
            }
            if (g + 1 < ntot) {
                int gn1 = g + 1;
                load_bslice(tnlist[gn1 >> 2], gn1 & 3, gn1 & 1);
                CPCOMMIT();
            }

            const uint32_t Bbase = smaddr(Bbuf0 + (g & 1) * BCHUNKB) + boff;
            const uint32_t Ac = Abase + (uint32_t)(c * 64 * 2);

            #pragma unroll
            for (int ks = 0; ks < 4; ks++) {
                const uint32_t kb = (uint32_t)(ks * 16 * 2);
                uint32_t af[4][4];
                uint32_t bf[4][2];
                #pragma unroll
                for (int mf = 0; mf < 4; mf++)
                    LDSM4(af[mf][0], af[mf][1], af[mf][2], af[mf][3],
                          Ac + (uint32_t)(mf * 16 * ASTRIDE * 2) + kb);
                #pragma unroll
                for (int p = 0; p < 2; p++)
                    LDSM4(bf[2 * p][0], bf[2 * p][1], bf[2 * p + 1][0], bf[2 * p + 1][1],
                          Bbase + (uint32_t)(p * 16 * HSTRIDE * 2) + kb);
                #pragma unroll
                for (int mf = 0; mf < 4; mf++)
                    #pragma unroll
                    for (int nf = 0; nf < 4; nf++)
                        mma16(acc[mf][nf], af[mf][0], af[mf][1], af[mf][2], af[mf][3],
                              bf[nf][0], bf[nf][1]);
            }
            g++;
        }

        // ---- epilogue: E = fp16(exp(logit)); stats from ROUNDED E ----
        #pragma unroll
        for (int mf = 0; mf < 4; mf++)
            #pragma unroll
            for (int h = 0; h < 2; h++) {
                int grow = m0 + wm * 64 + mf * 16 + 8 * h + gp;
                bool rok = grow < L_;
                float m = rmx[mf * 2 + h], s = rsm[mf * 2 + h];
                #pragma unroll
                for (int nf = 0; nf < 4; nf++) {
                    float ex = __expf(acc[mf][nf][2 * h]     * 10.0f);
                    float ey = __expf(acc[mf][nf][2 * h + 1] * 10.0f);
                    __half2 h2 = __floats2half2_rn(ex, ey);
                    float2 f2 = __half22float2(h2);
                    acc[mf][nf][2 * h]     = f2.x;
                    acc[mf][nf][2 * h + 1] = f2.y;
                    int scol = n0 + wn * 32 + nf * 8 + 2 * tg;
                    if (scol < S_) {
                        if (rok)
                            *reinterpret_cast<__half2*>(
                                &g_simh[((size_t)bb * L_ + grow) * S_ + scol]) = h2;
                        m = fmaxf(m, fmaxf(f2.x, f2.y));
                        s += f2.x + f2.y;
                    }
                }
                rmx[mf * 2 + h] = m;
                rsm[mf * 2 + h] = s;
            }

        // col partials over this warp's 64 rows -> atomic merge into final arrays
        #pragma unroll
        for (int nf = 0; nf < 4; nf++)
            #pragma unroll
            for (int ch = 0; ch < 2; ch++) {
                float m = neginf(), s = 0.f;
                #pragma unroll
                for (int mf = 0; mf < 4; mf++)
                    #pragma unroll
                    for (int h = 0; h < 2; h++) {
                        int grow = m0 + wm * 64 + mf * 16 + 8 * h + gp;
                        if (grow < L_) {
                            float v = acc[mf][nf][2 * h + ch];
                            m = fmaxf(m, v);
                            s += v;
                        }
                    }
                m  = fmaxf(m, __shfl_xor_sync(0xffffffffu, m, 4));
                m  = fmaxf(m, __shfl_xor_sync(0xffffffffu, m, 8));
                m  = fmaxf(m, __shfl_xor_sync(0xffffffffu, m, 16));
                s += __shfl_xor_sync(0xffffffffu, s, 4);
                s += __shfl_xor_sync(0xffffffffu, s, 8);
                s += __shfl_xor_sync(0xffffffffu, s, 16);
                if (gp == 0) {
                    int gs = n0 + wn * 32 + nf * 8 + 2 * tg + ch;
                    if (gs < S_) {
                        atomicMaxPosF(&g_cmax[bb * S_ + gs], m);
                        atomicAdd(&g_csum[bb * S_ + gs], s);
                    }
                }
            }
        // no CTA sync: warps/pairs proceed independently to the next tile
    }

    // ---- final row-stat merge (one per CTA, atomic across NSPLIT CTAs) ----
    __syncthreads();
    #pragma unroll
    for (int i = 0; i < 8; i++) {
        float m = rmx[i], s = rsm[i];
        m  = fmaxf(m, __shfl_xor_sync(0xffffffffu, m, 1));
        m  = fmaxf(m, __shfl_xor_sync(0xffffffffu, m, 2));
        s += __shfl_xor_sync(0xffffffffu, s, 1);
        s += __shfl_xor_sync(0xffffffffu, s, 2);
        if (tg == 0) {
            int rib = wm * 64 + (i >> 1) * 16 + (i & 1) * 8 + gp;
            red_m[wn * 128 + rib] = m;
            red_s[wn * 128 + rib] = s;
        }
    }
    __syncthreads();
    if (tid < 128) {
        float m = red_m[tid], s = red_s[tid];
        #pragma unroll
        for (int j = 1; j < 4; j++) {
            m = fmaxf(m, red_m[j * 128 + tid]);
            s += red_s[j * 128 + tid];
        }
        int gl = m0 + tid;
        if (gl < L_) {
            atomicMaxPosF(&g_rmax[bb * L_ + gl], m);
            atomicAdd(&g_rsum[bb * L_ + gl], s);
        }
    }
}

// ---------------- pass 4: conf planes + mask + mconf ----------------
__global__ __launch_bounds__(256) void finalize_kernel(float* __restrict__ out)
{
    const int NS4 = S_ / 4;
    int t = blockIdx.x * blockDim.x + threadIdx.x;
    if (t >= B_ * L_ * NS4) return;

    int s0  = (t % NS4) * 4;
    int rem = t / NS4;
    int l   = rem % L_;
    int bb  = rem / L_;

    bool in0 = g_bord0[l] != 0;
    uchar4 b1 = *reinterpret_cast<const uchar4*>(g_bord1 + s0);
    const unsigned char in1s[4] = {b1.x, b1.y, b1.z, b1.w};

    size_t base = ((size_t)bb * L_ + l) * S_ + s0;
    __half2 e01 = *reinterpret_cast<const __half2*>(g_simh + base);
    __half2 e23 = *reinterpret_cast<const __half2*>(g_simh + base + 2);
    float2 f01 = __half22float2(e01);
    float2 f23 = __half22float2(e23);

    float rm   = g_rmax[bb * L_ + l];
    float rinv = 1.0f / g_rsum[bb * L_ + l];
    float4 cm4 = *reinterpret_cast<const float4*>(g_cmax + bb * S_ + s0);
    float4 cs4 = *reinterpret_cast<const float4*>(g_csum + bb * S_ + s0);

    float c01v[4], c10v[4], mcv[4];
    const float Es4[4] = {f01.x, f01.y, f23.x, f23.y};
    const float cms[4] = {cm4.x, cm4.y, cm4.z, cm4.w};
    const float css[4] = {cs4.x, cs4.y, cs4.z, cs4.w};

    #pragma unroll
    for (int e = 0; e < 4; e++) {
        float E   = Es4[e];
        float c01 = E * rinv;
        float c10 = __fdividef(E, css[e]);
        bool mk   = in0 && (in1s[e] != 0) &&
                    ((c01 > 0.2f && E == rm) || (c10 > 0.2f && E == cms[e]));
        c01v[e] = c01;
        c10v[e] = c10;
        mcv[e]  = mk ? fmaxf(c01, c10) : 0.f;
    }

    const size_t P = (size_t)B_ * L_ * S_;
    __stcs(reinterpret_cast<float4*>(out + base),
           make_float4(c01v[0], c01v[1], c01v[2], c01v[3]));
    __stcs(reinterpret_cast<float4*>(out + P + base),
           make_float4(c10v[0], c10v[1], c10v[2], c10v[3]));
    __stcs(reinterpret_cast<float4*>(out + 2 * P + base),
           make_float4(mcv[0], mcv[1], mcv[2], mcv[3]));
}

// ---------------- launch ----------------
extern "C" void kernel_launch(void* const* d_in, const int* in_sizes, int n_in,
                              void* d_out, int out_size)
{
    const float* feat0 = (const float*)d_in[0];
    const float* feat1 = (const float*)d_in[1];
    const float* W     = (const float*)d_in[2];
    const float* bias  = (const float*)d_in[3];
    const int*   h0    = (const int*)d_in[4];
    const int*   w0    = (const int*)d_in[5];
    const int*   h1    = (const int*)d_in[6];
    const int*   w1    = (const int*)d_in[7];
    float* out = (float*)d_out;

    static bool configured = false;
    if (!configured) {
        cudaFuncSetAttribute(sim_kernel,
                             cudaFuncAttributeMaxDynamicSharedMemorySize, DYN_SZ);
        cudaFuncSetAttribute(proj_kernel,
                             cudaFuncAttributeMaxDynamicSharedMemorySize, PROJ_SMEM);
        configured = true;
    }

    init_kernel<<<(L_ + S_ + 255) / 256, 256>>>(h0, w0, h1, w1);          // idx 0
    proj_kernel<<<dim3(2, 75, 2), 256, PROJ_SMEM>>>(feat0, feat1, W, bias); // idx 1
    marker_kernel<<<1, 32>>>();                                           // idx 2
    sim_kernel<<<dim3(NSPLIT, NT_, B_), 256, DYN_SZ>>>();                 // idx 3 <- ncu target
    finalize_kernel<<<(B_ * L_ * (S_ / 4) + 255) / 256, 256>>>(out);      // idx 4
}

// round 16
// speedup vs baseline: 1.0400x; 1.0400x over previous
#include <cuda_runtime.h>
#include <cuda_fp16.h>
#include <cstdint>

#define B_ 2
#define L_ 4800
#define S_ 4800
#define C_ 256
#define NT_ 38          // n-tiles of 128
#define NSPLIT 4        // n-range splits -> 4*38*2 = 304 CTAs (2/SM, one wave)
#define SMPAD 36        // proj kernel smem pad (floats)
#define BL_ (B_ * L_)

// ---- sim kernel smem geometry (fp16, M=128 resident A) ----
#define ASTRIDE 264                      // halves per A smem row (256 data + 8 pad)
#define HSTRIDE 72                       // halves per B smem row (64 data + 8 pad)
#define ABYTES  (128 * ASTRIDE * 2)      // resident A tile: 67584 B
#define BCHUNKB (128 * HSTRIDE * 2)      // one B chunk: 18432 B
#define DYN_SZ  (ABYTES + 2 * BCHUNKB)   // 104448 B  (x2 CTAs = 204 KB/SM)

// ---------------- scratch (device globals: no allocs allowed) ----------------
__device__ __half g_f0h[B_ * L_ * C_];
__device__ __half g_f1h[B_ * S_ * C_];
__device__ __half g_simh[(size_t)B_ * L_ * S_];         // E = exp(logit), fp16 (92 MB)
__device__ float  g_rmax[BL_];
__device__ float  g_rsum[BL_];
__device__ float  g_cmax[B_ * S_];
__device__ float  g_csum[B_ * S_];
__device__ unsigned char g_bord0[L_];
__device__ unsigned char g_bord1[S_];
__device__ int    g_marker;

__device__ __forceinline__ float tf32r(float x) {
    uint32_t u = __float_as_uint(x);
    asm("cvt.rna.tf32.f32 %0, %0;" : "+r"(u));
    return __uint_as_float(u);
}

// tf32 m16n8k8 (proj only)
__device__ __forceinline__ void mma8(float d[4], const uint32_t a[4], const uint32_t b[2]) {
    asm volatile(
        "mma.sync.aligned.m16n8k8.row.col.f32.tf32.tf32.f32 "
        "{%0,%1,%2,%3}, {%4,%5,%6,%7}, {%8,%9}, {%0,%1,%2,%3};"
        : "+f"(d[0]), "+f"(d[1]), "+f"(d[2]), "+f"(d[3])
        : "r"(a[0]), "r"(a[1]), "r"(a[2]), "r"(a[3]), "r"(b[0]), "r"(b[1]));
}

// fp16 m16n8k16 (sim)
__device__ __forceinline__ void mma16(float d[4], uint32_t a0, uint32_t a1,
                                      uint32_t a2, uint32_t a3,
                                      uint32_t b0, uint32_t b1) {
    asm volatile(
        "mma.sync.aligned.m16n8k16.row.col.f32.f16.f16.f32 "
        "{%0,%1,%2,%3}, {%4,%5,%6,%7}, {%8,%9}, {%0,%1,%2,%3};"
        : "+f"(d[0]), "+f"(d[1]), "+f"(d[2]), "+f"(d[3])
        : "r"(a0), "r"(a1), "r"(a2), "r"(a3), "r"(b0), "r"(b1));
}

#define LDSM4(r0, r1, r2, r3, addr)                                            \
    asm volatile("ldmatrix.sync.aligned.m8n8.x4.shared.b16 {%0,%1,%2,%3}, [%4];" \
                 : "=r"(r0), "=r"(r1), "=r"(r2), "=r"(r3) : "r"(addr))

__device__ __forceinline__ float neginf() { return __int_as_float(0xff800000); }

__device__ __forceinline__ uint32_t smaddr(const void* p) {
    return (uint32_t)__cvta_generic_to_shared(p);
}

#define CP16(dst, src, pred)                                                   \
    asm volatile("cp.async.cg.shared.global [%0], [%1], 16, %2;\n" ::          \
                     "r"(dst), "l"(src), "r"((pred) ? 16 : 0))
#define CPCOMMIT() asm volatile("cp.async.commit_group;\n")
#define CPWAIT0()  asm volatile("cp.async.wait_group 0;\n")
#define PAIRBAR(id) asm volatile("bar.sync %0, 64;" :: "r"(id) : "memory")

// atomic max for strictly-positive floats via int bit-pattern ordering
__device__ __forceinline__ void atomicMaxPosF(float* addr, float v) {
    atomicMax(reinterpret_cast<int*>(addr), __float_as_int(v));
}

// ---------------- idx 0: border masks + zero stats (+ marker) ----------------
__global__ void init_kernel(const int* __restrict__ ph0, const int* __restrict__ pw0,
                            const int* __restrict__ ph1, const int* __restrict__ pw1)
{
    int h0 = __ldg(ph0), w0 = __ldg(pw0), h1 = __ldg(ph1), w1 = __ldg(pw1);
    int i = blockIdx.x * blockDim.x + threadIdx.x;
    if (i == 0) g_marker = 1;
    if (i < L_) {
        int r = i / w0, c = i - r * w0;
        g_bord0[i] = (r >= 2 && r < h0 - 2 && c >= 2 && c < w0 - 2) ? 1 : 0;
    } else if (i < L_ + S_) {
        int s = i - L_;
        int r = s / w1, c = s - r * w1;
        g_bord1[s] = (r >= 2 && r < h1 - 2 && c >= 2 && c < w1 - 2) ? 1 : 0;
    }
    // zero the atomic accumulators (every call: graph replays reuse them)
    if (i < BL_) {                  // B_*S_ == BL_
        g_rmax[i] = 0.f;
        g_rsum[i] = 0.f;
        g_cmax[i] = 0.f;
        g_csum[i] = 0.f;
    }
}

// ================= proj (tf32, static smem, fused both inputs) =================
__global__ __launch_bounds__(256) void proj_kernel(
    const float* __restrict__ X0, const float* __restrict__ X1,
    const float* __restrict__ W, const float* __restrict__ bias)
{
    __shared__ float As[128 * SMPAD];
    __shared__ float Bs[128 * SMPAD];
    float acc[4][4][4] = {};

    const int which = blockIdx.z;
    const float* A = which ? X1 : X0;
    const int n0 = blockIdx.x * 128;
    const int m0 = blockIdx.y * 128;

    const int tid  = threadIdx.x;
    const int lane = tid & 31;
    const int warp = tid >> 5;
    const int wm = warp >> 2, wn = warp & 3;
    const int gp = lane >> 2, tg = lane & 3;

    for (int kc = 0; kc < C_; kc += 32) {
        #pragma unroll
        for (int i = 0; i < 4; i++) {
            int idx = tid + i * 256;
            int r   = idx >> 3;
            int kq  = (idx & 7) * 4;
            float4 va = *reinterpret_cast<const float4*>(A + (size_t)(m0 + r) * C_ + kc + kq);
            va.x = tf32r(va.x); va.y = tf32r(va.y); va.z = tf32r(va.z); va.w = tf32r(va.w);
            *reinterpret_cast<float4*>(As + r * SMPAD + kq) = va;
            float4 vb = *reinterpret_cast<const float4*>(W + (size_t)(n0 + r) * C_ + kc + kq);
            vb.x = tf32r(vb.x); vb.y = tf32r(vb.y); vb.z = tf32r(vb.z); vb.w = tf32r(vb.w);
            *reinterpret_cast<float4*>(Bs + r * SMPAD + kq) = vb;
        }
        __syncthreads();
        #pragma unroll
        for (int ks = 0; ks < 4; ks++) {
            const int k0 = ks * 8;
            uint32_t afr[4][4];
            uint32_t bfr[4][2];
            #pragma unroll
            for (int mf = 0; mf < 4; mf++) {
                const float* p = As + (wm * 64 + mf * 16 + gp) * SMPAD + k0 + tg;
                afr[mf][0] = __float_as_uint(p[0]);
                afr[mf][1] = __float_as_uint(p[8 * SMPAD]);
                afr[mf][2] = __float_as_uint(p[4]);
                afr[mf][3] = __float_as_uint(p[8 * SMPAD + 4]);
            }
            #pragma unroll
            for (int nf = 0; nf < 4; nf++) {
                const float* p = Bs + (wn * 32 + nf * 8 + gp) * SMPAD + k0 + tg;
                bfr[nf][0] = __float_as_uint(p[0]);
                bfr[nf][1] = __float_as_uint(p[4]);
            }
            #pragma unroll
            for (int mf = 0; mf < 4; mf++)
                #pragma unroll
                for (int nf = 0; nf < 4; nf++)
                    mma8(acc[mf][nf], afr[mf], bfr[nf]);
        }
        __syncthreads();
    }

    __half* O = which ? g_f1h : g_f0h;
    #pragma unroll
    for (int mf = 0; mf < 4; mf++) {
        int row = m0 + wm * 64 + mf * 16 + gp;
        #pragma unroll
        for (int nf = 0; nf < 4; nf++) {
            int col = n0 + wn * 32 + nf * 8 + 2 * tg;
            float b0 = __ldg(bias + col), b1 = __ldg(bias + col + 1);
            #pragma unroll
            for (int h = 0; h < 2; h++) {
                __half2 v = __floats2half2_rn(
                    (acc[mf][nf][2 * h]     + b0) * 0.0625f,
                    (acc[mf][nf][2 * h + 1] + b1) * 0.0625f);
                *reinterpret_cast<__half2*>(O + (size_t)(row + 8 * h) * C_ + col) = v;
            }
        }
    }
}

// ======== sim (persistent-A M=128, pair barriers, atomic stats, fp16 E) ========
__global__ __launch_bounds__(256, 2) void sim_kernel()
{
    extern __shared__ char dynp[];          // [A tile | B buf0 | B buf1]
    __shared__ float red_m[4 * 128];
    __shared__ float red_s[4 * 128];

    const int sidx = blockIdx.x;            // n-range split
    const int tm   = blockIdx.y;
    const int bb   = blockIdx.z;
    const int m0   = tm * 128;
    const __half* A  = g_f0h + (size_t)bb * L_ * C_;
    const __half* Bm = g_f1h + (size_t)bb * S_ * C_;

    const int tid  = threadIdx.x;
    const int lane = tid & 31;
    const int warp = tid >> 5;
    const int wm = warp >> 2, wn = warp & 3;
    const int gp = lane >> 2, tg = lane & 3;

    __half* Asm = (__half*)dynp;
    char*   Bbuf0 = dynp + ABYTES;

    // ---- resident A tile load ----
    {
        const int r    = tid >> 1;
        const int half = tid & 1;
        int gr = m0 + r; bool oa = gr < L_;
        const __half* arow = A + (size_t)(oa ? gr : 0) * C_;
        #pragma unroll
        for (int i = 0; i < 16; i++) {
            int seg = half * 16 + i;
            CP16(smaddr(Asm + r * ASTRIDE + seg * 8), arow + seg * 8, oa);
        }
    }
    CPCOMMIT();

    // ---- per-pair B slice loader ----
    const int tp   = wm * 32 + lane;
    const int brow = wn * 32 + (tp >> 1);
    const int bq0  = (tp & 1) * 4;
    auto load_bslice = [&](int tn, int c, int buf) {
        __half* Bb = (__half*)(Bbuf0 + buf * BCHUNKB);
        const int kc = c * 64;
        int gn = tn * 128 + brow; bool ob = gn < S_;
        const __half* brw = Bm + (size_t)(ob ? gn : 0) * C_ + kc;
        #pragma unroll
        for (int q = 0; q < 4; q++) {
            int kk = (bq0 + q) * 8;
            CP16(smaddr(Bb + brow * HSTRIDE + kk), brw + kk, ob);
        }
    };

    const uint32_t aoff = (uint32_t)((wm * 64 + (lane & 15)) * ASTRIDE + (lane >> 4) * 8) * 2;
    const uint32_t boff = (uint32_t)((wn * 32 + (lane & 7) + ((lane >> 4) & 1) * 8) * HSTRIDE
                                     + ((lane >> 3) & 1) * 8) * 2;
    const uint32_t Abase = smaddr(Asm) + aoff;

    int tnlist[10];
    int ntn = 0;
    for (int tn = sidx; tn < NT_; tn += NSPLIT) tnlist[ntn++] = tn;

    load_bslice(tnlist[0], 0, 0);
    CPCOMMIT();

    CPWAIT0();
    __syncthreads();    // publish A (one-time)

    float rmx[8], rsm[8];
    #pragma unroll
    for (int i = 0; i < 8; i++) { rmx[i] = neginf(); rsm[i] = 0.f; }

    const int ntot = ntn * 4;
    const int barid = wn + 1;
    int g = 0;

    for (int ti = 0; ti < ntn; ti++) {
        const int tn = tnlist[ti];
        const int n0 = tn * 128;
        float acc[4][4][4] = {};

        #pragma unroll
        for (int c = 0; c < 4; c++) {
            if (g > 0) {
                CPWAIT0();
                PAIRBAR(barid);
            }
            if (g + 1 < ntot) {
                int gn1 = g + 1;
                load_bslice(tnlist[gn1 >> 2], gn1 & 3, gn1 & 1);
                CPCOMMIT();
            }

            const uint32_t Bbase = smaddr(Bbuf0 + (g & 1) * BCHUNKB) + boff;
            const uint32_t Ac = Abase + (uint32_t)(c * 64 * 2);

            #pragma unroll
            for (int ks = 0; ks < 4; ks++) {
                const uint32_t kb = (uint32_t)(ks * 16 * 2);
                uint32_t af[4][4];
                uint32_t bf[4][2];
                #pragma unroll
                for (int mf = 0; mf < 4; mf++)
                    LDSM4(af[mf][0], af[mf][1], af[mf][2], af[mf][3],
                          Ac + (uint32_t)(mf * 16 * ASTRIDE * 2) + kb);
                #pragma unroll
                for (int p = 0; p < 2; p++)
                    LDSM4(bf[2 * p][0], bf[2 * p][1], bf[2 * p + 1][0], bf[2 * p + 1][1],
                          Bbase + (uint32_t)(p * 16 * HSTRIDE * 2) + kb);
                #pragma unroll
                for (int mf = 0; mf < 4; mf++)
                    #pragma unroll
                    for (int nf = 0; nf < 4; nf++)
                        mma16(acc[mf][nf], af[mf][0], af[mf][1], af[mf][2], af[mf][3],
                              bf[nf][0], bf[nf][1]);
            }
            g++;
        }

        // ---- epilogue: E = fp16(exp(logit)); stats from ROUNDED E ----
        #pragma unroll
        for (int mf = 0; mf < 4; mf++)
            #pragma unroll
            for (int h = 0; h < 2; h++) {
                int grow = m0 + wm * 64 + mf * 16 + 8 * h + gp;
                bool rok = grow < L_;
                float m = rmx[mf * 2 + h], s = rsm[mf * 2 + h];
                #pragma unroll
                for (int nf = 0; nf < 4; nf++) {
                    float ex = __expf(acc[mf][nf][2 * h]     * 10.0f);
                    float ey = __expf(acc[mf][nf][2 * h + 1] * 10.0f);
                    __half2 h2 = __floats2half2_rn(ex, ey);
                    float2 f2 = __half22float2(h2);
                    acc[mf][nf][2 * h]     = f2.x;
                    acc[mf][nf][2 * h + 1] = f2.y;
                    int scol = n0 + wn * 32 + nf * 8 + 2 * tg;
                    if (scol < S_) {
                        if (rok)
                            *reinterpret_cast<__half2*>(
                                &g_simh[((size_t)bb * L_ + grow) * S_ + scol]) = h2;
                        m = fmaxf(m, fmaxf(f2.x, f2.y));
                        s += f2.x + f2.y;
                    }
                }
                rmx[mf * 2 + h] = m;
                rsm[mf * 2 + h] = s;
            }

        // col partials over this warp's 64 rows -> atomic merge into final arrays
        #pragma unroll
        for (int nf = 0; nf < 4; nf++)
            #pragma unroll
            for (int ch = 0; ch < 2; ch++) {
                float m = neginf(), s = 0.f;
                #pragma unroll
                for (int mf = 0; mf < 4; mf++)
                    #pragma unroll
                    for (int h = 0; h < 2; h++) {
                        int grow = m0 + wm * 64 + mf * 16 + 8 * h + gp;
                        if (grow < L_) {
                            float v = acc[mf][nf][2 * h + ch];
                            m = fmaxf(m, v);
                            s += v;
                        }
                    }
                m  = fmaxf(m, __shfl_xor_sync(0xffffffffu, m, 4));
                m  = fmaxf(m, __shfl_xor_sync(0xffffffffu, m, 8));
                m  = fmaxf(m, __shfl_xor_sync(0xffffffffu, m, 16));
                s += __shfl_xor_sync(0xffffffffu, s, 4);
                s += __shfl_xor_sync(0xffffffffu, s, 8);
                s += __shfl_xor_sync(0xffffffffu, s, 16);
                if (gp == 0) {
                    int gs = n0 + wn * 32 + nf * 8 + 2 * tg + ch;
                    if (gs < S_) {
                        atomicMaxPosF(&g_cmax[bb * S_ + gs], m);
                        atomicAdd(&g_csum[bb * S_ + gs], s);
                    }
                }
            }
        // no CTA sync: warps/pairs proceed independently to the next tile
    }

    // ---- final row-stat merge (one per CTA, atomic across NSPLIT CTAs) ----
    __syncthreads();
    #pragma unroll
    for (int i = 0; i < 8; i++) {
        float m = rmx[i], s = rsm[i];
        m  = fmaxf(m, __shfl_xor_sync(0xffffffffu, m, 1));
        m  = fmaxf(m, __shfl_xor_sync(0xffffffffu, m, 2));
        s += __shfl_xor_sync(0xffffffffu, s, 1);
        s += __shfl_xor_sync(0xffffffffu, s, 2);
        if (tg == 0) {
            int rib = wm * 64 + (i >> 1) * 16 + (i & 1) * 8 + gp;
            red_m[wn * 128 + rib] = m;
            red_s[wn * 128 + rib] = s;
        }
    }
    __syncthreads();
    if (tid < 128) {
        float m = red_m[tid], s = red_s[tid];
        #pragma unroll
        for (int j = 1; j < 4; j++) {
            m = fmaxf(m, red_m[j * 128 + tid]);
            s += red_s[j * 128 + tid];
        }
        int gl = m0 + tid;
        if (gl < L_) {
            atomicMaxPosF(&g_rmax[bb * L_ + gl], m);
            atomicAdd(&g_rsum[bb * L_ + gl], s);
        }
    }
}

// ---------------- idx 3: conf planes + mask + mconf ----------------
__global__ __launch_bounds__(256) void finalize_kernel(float* __restrict__ out)
{
    const int NS4 = S_ / 4;
    int t = blockIdx.x * blockDim.x + threadIdx.x;
    if (t >= B_ * L_ * NS4) return;

    int s0  = (t % NS4) * 4;
    int rem = t / NS4;
    int l   = rem % L_;
    int bb  = rem / L_;

    bool in0 = g_bord0[l] != 0;
    uchar4 b1 = *reinterpret_cast<const uchar4*>(g_bord1 + s0);
    const unsigned char in1s[4] = {b1.x, b1.y, b1.z, b1.w};

    size_t base = ((size_t)bb * L_ + l) * S_ + s0;
    __half2 e01 = *reinterpret_cast<const __half2*>(g_simh + base);
    __half2 e23 = *reinterpret_cast<const __half2*>(g_simh + base + 2);
    float2 f01 = __half22float2(e01);
    float2 f23 = __half22float2(e23);

    float rm   = g_rmax[bb * L_ + l];
    float rinv = 1.0f / g_rsum[bb * L_ + l];
    float4 cm4 = *reinterpret_cast<const float4*>(g_cmax + bb * S_ + s0);
    float4 cs4 = *reinterpret_cast<const float4*>(g_csum + bb * S_ + s0);

    float c01v[4], c10v[4], mcv[4];
    const float Es4[4] = {f01.x, f01.y, f23.x, f23.y};
    const float cms[4] = {cm4.x, cm4.y, cm4.z, cm4.w};
    const float css[4] = {cs4.x, cs4.y, cs4.z, cs4.w};

    #pragma unroll
    for (int e = 0; e < 4; e++) {
        float E   = Es4[e];
        float c01 = E * rinv;
        float c10 = __fdividef(E, css[e]);
        bool mk   = in0 && (in1s[e] != 0) &&
                    ((c01 > 0.2f && E == rm) || (c10 > 0.2f && E == cms[e]));
        c01v[e] = c01;
        c10v[e] = c10;
        mcv[e]  = mk ? fmaxf(c01, c10) : 0.f;
    }

    const size_t P = (size_t)B_ * L_ * S_;
    __stcs(reinterpret_cast<float4*>(out + base),
           make_float4(c01v[0], c01v[1], c01v[2], c01v[3]));
    __stcs(reinterpret_cast<float4*>(out + P + base),
           make_float4(c10v[0], c10v[1], c10v[2], c10v[3]));
    __stcs(reinterpret_cast<float4*>(out + 2 * P + base),
           make_float4(mcv[0], mcv[1], mcv[2], mcv[3]));
}

// ---------------- launch ----------------
extern "C" void kernel_launch(void* const* d_in, const int* in_sizes, int n_in,
                              void* d_out, int out_size)
{
    const float* feat0 = (const float*)d_in[0];
    const float* feat1 = (const float*)d_in[1];
    const float* W     = (const float*)d_in[2];
    const float* bias  = (const float*)d_in[3];
    const int*   h0    = (const int*)d_in[4];
    const int*   w0    = (const int*)d_in[5];
    const int*   h1    = (const int*)d_in[6];
    const int*   w1    = (const int*)d_in[7];
    float* out = (float*)d_out;

    static bool configured = false;
    if (!configured) {
        cudaFuncSetAttribute(sim_kernel,
                             cudaFuncAttributeMaxDynamicSharedMemorySize, DYN_SZ);
        configured = true;
    }

    init_kernel<<<(L_ + S_ + 255) / 256, 256>>>(h0, w0, h1, w1);       // idx 0
    proj_kernel<<<dim3(2, 75, 2), 256>>>(feat0, feat1, W, bias);       // idx 1
    sim_kernel<<<dim3(NSPLIT, NT_, B_), 256, DYN_SZ>>>();              // idx 2
    finalize_kernel<<<(B_ * L_ * (S_ / 4) + 255) / 256, 256>>>(out);   // idx 3 <- ncu target
}